// round 14
// baseline (speedup 1.0000x reference)
#include <cuda_runtime.h>
#include <cstdint>

#define NN 100000
#define NE 3200000
#define H  32
#define EPT 3   // edges per thread

typedef unsigned long long ull;

// __device__ scratch (no allocations allowed)
__device__ float4 g_L1q[H];                       // (A,B,C,0): h1 = relu(A*n + B*t + C)
__device__ __align__(16) float4 g_sums4[NN];      // xyz = sums, w = count

// ---- packed f32x2 helpers (ptxas will not auto-fuse these) ----
__device__ __forceinline__ ull ffma2(ull a, ull b, ull c) {
    ull d;
    asm("fma.rn.f32x2 %0, %1, %2, %3;" : "=l"(d) : "l"(a), "l"(b), "l"(c));
    return d;
}
__device__ __forceinline__ ull fmul2(ull a, ull b) {
    ull d;
    asm("mul.rn.f32x2 %0, %1, %2;" : "=l"(d) : "l"(a), "l"(b));
    return d;
}
__device__ __forceinline__ ull fadd2(ull a, ull b) {
    ull d;
    asm("add.rn.f32x2 %0, %1, %2;" : "=l"(d) : "l"(a), "l"(b));
    return d;
}
__device__ __forceinline__ ull pack2(float lo, float hi) {
    ull r;
    asm("mov.b64 %0, {%1, %2};" : "=l"(r) : "f"(lo), "f"(hi));
    return r;
}
__device__ __forceinline__ float2 unpack2(ull v) {
    float2 f;
    asm("mov.b64 {%0, %1}, %2;" : "=f"(f.x), "=f"(f.y) : "l"(v));
    return f;
}
__device__ __forceinline__ ull relu2(ull v) {
    float2 f = unpack2(v);
    return pack2(fmaxf(f.x, 0.0f), fmaxf(f.y, 0.0f));
}

// ---------------------------------------------------------------------------
__global__ void prep_kernel(const float* __restrict__ W1,
                            const float* __restrict__ gamma,
                            const float* __restrict__ beta,
                            const float* __restrict__ mean,
                            const float* __restrict__ var) {
    int k = threadIdx.x;
    if (k < H) {
        float s = gamma[k] * rsqrtf(var[k] + 1e-5f);
        g_L1q[k] = make_float4(W1[k] * s, W1[H + k] * s, beta[k] - mean[k] * s, 0.0f);
    }
}

__global__ void zero_kernel() {
    int i = blockIdx.x * blockDim.x + threadIdx.x;
    if (i < NN) g_sums4[i] = make_float4(0.0f, 0.0f, 0.0f, 0.0f);
}

// ---------------------------------------------------------------------------
// THREE edges per thread: every shared weight row LDS serves 3 edges
// (smem-crossbar traffic is the binding resource: broadcast LDS.128 costs
//  4 wavefronts, no dedup — fewer row reads per edge is the only lever).
__global__ void __launch_bounds__(256, 2) edge_kernel(
    const float* __restrict__ x,
    const int* __restrict__ ei,
    const float* __restrict__ W2, const float* __restrict__ b2,
    const float* __restrict__ W3, const float* __restrict__ b3,
    const float* __restrict__ W4,
    const float* __restrict__ W5, const float* __restrict__ b5,
    float* __restrict__ out_m)
{
    __shared__ __align__(16) float sW2[H * H];    // row-major [j][k]
    __shared__ __align__(16) float sW3T[H * H];   // transposed [k][j]
    __shared__ __align__(16) float4 sL1[H];
    __shared__ __align__(16) float sb2[H], sb3[H], sW4[H], sW5[H];
    __shared__ float sb5v;

    int tid = threadIdx.x;
    for (int t = tid; t < H * H; t += 256) {
        sW2[t] = W2[t];
        int k = t >> 5, j = t & 31;
        sW3T[t] = W3[j * H + k];
    }
    if (tid < H) {
        sL1[tid] = g_L1q[tid];
        sb2[tid] = b2[tid];
        sb3[tid] = b3[tid];
        sW4[tid] = W4[tid];
        sW5[tid] = W5[tid];
    }
    if (tid == 0) sb5v = b5[0];
    __syncthreads();

    long e0 = ((long)blockIdx.x * 256 + tid) * EPT;

    int ni[EPT], nj[EPT];
    bool val[EPT];
#pragma unroll
    for (int c = 0; c < EPT; c++) {
        long e = e0 + c;
        bool ok = (e < NE);
        int a = ok ? ei[e] : 0;
        int b = ok ? ei[NE + e] : 0;
        ok = ok && ((unsigned)a < NN) && ((unsigned)b < NN);
        ni[c] = a; nj[c] = b; val[c] = ok;
    }

    float d0[EPT], d1[EPT], d2[EPT], nrm[EPT], dts[EPT];
#pragma unroll
    for (int c = 0; c < EPT; c++) {
        float xi0 = __ldg(&x[3 * ni[c] + 0]), xi1 = __ldg(&x[3 * ni[c] + 1]), xi2 = __ldg(&x[3 * ni[c] + 2]);
        float xj0 = __ldg(&x[3 * nj[c] + 0]), xj1 = __ldg(&x[3 * nj[c] + 1]), xj2 = __ldg(&x[3 * nj[c] + 2]);
        d0[c] = xi0 - xj0; d1[c] = xi1 - xj1; d2[c] = xi2 - xj2;
        float nsq = d0[c] * d0[c] + d1[c] * d1[c] + d2[c] * d2[c];
        float dot = xi0 * xj0 + xi1 * xj1 + xi2 * xj2;
        nrm[c] = log1pf(nsq);
        dts[c] = copysignf(log1pf(fabsf(dot)), dot);
    }

    // ---- fused layer1 + layer2: acc[c] = b2 + sum_j relu(l1_j(c)) * W2[j,:] ----
    ull acc[EPT][H / 2];
    {
        const ull* b2p = (const ull*)sb2;
#pragma unroll
        for (int q = 0; q < H / 2; q++) {
            ull b = b2p[q];
#pragma unroll
            for (int c = 0; c < EPT; c++) acc[c][q] = b;
        }
    }
#pragma unroll 2
    for (int j = 0; j < H; j++) {
        float4 cf = sL1[j];
        ull hp[EPT];
#pragma unroll
        for (int c = 0; c < EPT; c++) {
            float h = fmaxf(fmaf(nrm[c], cf.x, fmaf(dts[c], cf.y, cf.z)), 0.0f);
            hp[c] = pack2(h, h);
        }
        const ulonglong2* row = (const ulonglong2*)(sW2 + j * H);
#pragma unroll
        for (int q = 0; q < H / 4; q++) {
            ulonglong2 w = row[q];                 // one LDS, three edges
#pragma unroll
            for (int c = 0; c < EPT; c++) {
                acc[c][2 * q + 0] = ffma2(hp[c], w.x, acc[c][2 * q + 0]);
                acc[c][2 * q + 1] = ffma2(hp[c], w.y, acc[c][2 * q + 1]);
            }
        }
    }

    // ---- h2 = relu(acc) IN PLACE ----
#pragma unroll
    for (int c = 0; c < EPT; c++)
#pragma unroll
        for (int q = 0; q < H / 2; q++) acc[c][q] = relu2(acc[c][q]);

    // ---- gate: wgt = sigmoid(h2 . W5 + b5) ----
    float wgt[EPT];
    {
        const ull* w5p = (const ull*)sW5;
#pragma unroll
        for (int c = 0; c < EPT; c++) {
            ull z0 = 0, z1 = 0;
#pragma unroll
            for (int q = 0; q < H / 2; q += 2) {
                z0 = ffma2(acc[c][q], w5p[q], z0);
                z1 = ffma2(acc[c][q + 1], w5p[q + 1], z1);
            }
            float2 f = unpack2(fadd2(z0, z1));
            wgt[c] = 1.0f / (1.0f + expf(-(f.x + f.y + sb5v)));
        }
    }

    // ---- m = h2 * wgt, write out ----
#pragma unroll
    for (int c = 0; c < EPT; c++) {
        if (!val[c]) continue;
        ull wp = pack2(wgt[c], wgt[c]);
        ulonglong2* mo = (ulonglong2*)(out_m + (e0 + c) * H);
#pragma unroll
        for (int q = 0; q < H / 4; q++) {
            ulonglong2 v;
            v.x = fmul2(acc[c][2 * q + 0], wp);
            v.y = fmul2(acc[c][2 * q + 1], wp);
            mo[q] = v;
        }
    }

    // ---- phi_x, k-outer vs transposed W3; each row LDS serves 3 edges ----
    float phix[EPT];
#pragma unroll
    for (int c = 0; c < EPT; c++) phix[c] = 0.0f;
#pragma unroll 2
    for (int k = 0; k < H; k++) {
        const ulonglong2* row = (const ulonglong2*)(sW3T + k * H);
        ull s0[EPT], s1[EPT];
#pragma unroll
        for (int c = 0; c < EPT; c++) { s0[c] = 0; s1[c] = 0; }
#pragma unroll
        for (int q = 0; q < H / 4; q++) {
            ulonglong2 w = row[q];                 // one LDS, three edges
#pragma unroll
            for (int c = 0; c < EPT; c++) {
                s0[c] = ffma2(acc[c][2 * q + 0], w.x, s0[c]);
                s1[c] = ffma2(acc[c][2 * q + 1], w.y, s1[c]);
            }
        }
        float b3k = sb3[k], w4k = sW4[k];
#pragma unroll
        for (int c = 0; c < EPT; c++) {
            float2 f = unpack2(fadd2(s0[c], s1[c]));
            float u = fmaxf(fmaf(wgt[c], f.x + f.y, b3k), 0.0f);
            phix[c] = fmaf(u, w4k, phix[c]);
        }
    }

    // ---- scatter-mean: scalar reductions onto the float4 cell ----
#pragma unroll
    for (int c = 0; c < EPT; c++) {
        if (!val[c]) continue;
        float u0 = fminf(fmaxf(d0[c] * phix[c], -100.0f), 100.0f);
        float u1 = fminf(fmaxf(d1[c] * phix[c], -100.0f), 100.0f);
        float u2 = fminf(fmaxf(d2[c] * phix[c], -100.0f), 100.0f);
        float* cell = (float*)&g_sums4[ni[c]];
        atomicAdd(cell + 0, u0);
        atomicAdd(cell + 1, u1);
        atomicAdd(cell + 2, u2);
        atomicAdd(cell + 3, 1.0f);
    }
}

// ---------------------------------------------------------------------------
__global__ void node_kernel(const float* __restrict__ x, float* __restrict__ out_x) {
    int n = blockIdx.x * blockDim.x + threadIdx.x;
    if (n < NN) {
        float4 s = g_sums4[n];
        float inv = 1.0f / fmaxf(s.w, 1.0f);
        out_x[3 * n + 0] = x[3 * n + 0] + s.x * inv;
        out_x[3 * n + 1] = x[3 * n + 1] + s.y * inv;
        out_x[3 * n + 2] = x[3 * n + 2] + s.z * inv;
    }
}

// ---------------------------------------------------------------------------
extern "C" void kernel_launch(void* const* d_in, const int* in_sizes, int n_in,
                              void* d_out, int out_size) {
    const float* x   = (const float*)d_in[0];
    const int*   ei  = (const int*)d_in[1];     // int32 (jax default x64-disabled)
    const float* W1  = (const float*)d_in[2];
    const float* gma = (const float*)d_in[3];
    const float* bta = (const float*)d_in[4];
    const float* mea = (const float*)d_in[5];
    const float* var = (const float*)d_in[6];
    const float* W2  = (const float*)d_in[7];
    const float* b2  = (const float*)d_in[8];
    const float* W3  = (const float*)d_in[9];
    const float* b3  = (const float*)d_in[10];
    const float* W4  = (const float*)d_in[11];
    const float* W5  = (const float*)d_in[12];
    const float* b5  = (const float*)d_in[13];

    float* out_x = (float*)d_out;          // x_tilde: [NN, 3]
    float* out_m = out_x + (long)NN * 3;   // m: [NE, H]

    zero_kernel<<<(NN + 255) / 256, 256>>>();
    prep_kernel<<<1, 32>>>(W1, gma, bta, mea, var);
    int threads = (NE + EPT - 1) / EPT;
    edge_kernel<<<(threads + 255) / 256, 256>>>(x, ei, W2, b2, W3, b3, W4, W5, b5, out_m);
    node_kernel<<<(NN + 255) / 256, 256>>>(x, out_x);
}

// round 16
// speedup vs baseline: 1.3411x; 1.3411x over previous
#include <cuda_runtime.h>
#include <cstdint>

#define NN 100000
#define NE 3200000
#define H  32

typedef unsigned long long ull;

// __device__ scratch (no allocations allowed)
__device__ float4 g_L1q[H];                       // (A,B,C,0): h1 = relu(A*n + B*t + C)
__device__ __align__(16) float4 g_sums4[NN];      // xyz = sums, w = count

// ---- packed f32x2 helpers (ptxas will not auto-fuse these) ----
__device__ __forceinline__ ull ffma2(ull a, ull b, ull c) {
    ull d;
    asm("fma.rn.f32x2 %0, %1, %2, %3;" : "=l"(d) : "l"(a), "l"(b), "l"(c));
    return d;
}
__device__ __forceinline__ ull fmul2(ull a, ull b) {
    ull d;
    asm("mul.rn.f32x2 %0, %1, %2;" : "=l"(d) : "l"(a), "l"(b));
    return d;
}
__device__ __forceinline__ ull fadd2(ull a, ull b) {
    ull d;
    asm("add.rn.f32x2 %0, %1, %2;" : "=l"(d) : "l"(a), "l"(b));
    return d;
}
__device__ __forceinline__ ull pack2(float lo, float hi) {
    ull r;
    asm("mov.b64 %0, {%1, %2};" : "=l"(r) : "f"(lo), "f"(hi));
    return r;
}
__device__ __forceinline__ float2 unpack2(ull v) {
    float2 f;
    asm("mov.b64 {%0, %1}, %2;" : "=f"(f.x), "=f"(f.y) : "l"(v));
    return f;
}

// ---------------------------------------------------------------------------
__global__ void prep_kernel(const float* __restrict__ W1,
                            const float* __restrict__ gamma,
                            const float* __restrict__ beta,
                            const float* __restrict__ mean,
                            const float* __restrict__ var) {
    int k = threadIdx.x;
    if (k < H) {
        float s = gamma[k] * rsqrtf(var[k] + 1e-5f);
        g_L1q[k] = make_float4(W1[k] * s, W1[H + k] * s, beta[k] - mean[k] * s, 0.0f);
    }
}

__global__ void zero_kernel() {
    int i = blockIdx.x * blockDim.x + threadIdx.x;
    if (i < NN) g_sums4[i] = make_float4(0.0f, 0.0f, 0.0f, 0.0f);
}

// ---------------------------------------------------------------------------
// TWO edges per thread (R8 config = best known). blk0 allows the grid to be
// split into two sequential launches so ncu's -s 5 -c 1 lands on this kernel.
__global__ void __launch_bounds__(256, 2) edge_kernel(
    const float* __restrict__ x,
    const int* __restrict__ ei,
    const float* __restrict__ W2, const float* __restrict__ b2,
    const float* __restrict__ W3, const float* __restrict__ b3,
    const float* __restrict__ W4,
    const float* __restrict__ W5, const float* __restrict__ b5,
    float* __restrict__ out_m, int blk0)
{
    __shared__ __align__(16) float sW2[H * H];    // row-major [j][k]
    __shared__ __align__(16) float sW3T[H * H];   // transposed [k][j]
    __shared__ __align__(16) float4 sL1[H];
    __shared__ __align__(16) float sb2[H], sb3[H], sW4[H], sW5[H];
    __shared__ float sb5v;

    int tid = threadIdx.x;
    for (int t = tid; t < H * H; t += 256) {
        sW2[t] = W2[t];
        int k = t >> 5, j = t & 31;
        sW3T[t] = W3[j * H + k];
    }
    if (tid < H) {
        sL1[tid] = g_L1q[tid];
        sb2[tid] = b2[tid];
        sb3[tid] = b3[tid];
        sW4[tid] = W4[tid];
        sW5[tid] = W5[tid];
    }
    if (tid == 0) sb5v = b5[0];
    __syncthreads();

    long e0 = ((long)(blockIdx.x + blk0) * 256 + tid) * 2;
    long e1 = e0 + 1;

    int2 di = *(const int2*)(ei + e0);
    int2 sj = *(const int2*)(ei + (long)NE + e0);
    int ia = di.x, ib = di.y, ja = sj.x, jb = sj.y;
    if ((unsigned)ia >= NN || (unsigned)ib >= NN ||
        (unsigned)ja >= NN || (unsigned)jb >= NN) return;

    float xa0 = __ldg(&x[3 * ia + 0]), xa1 = __ldg(&x[3 * ia + 1]), xa2 = __ldg(&x[3 * ia + 2]);
    float ya0 = __ldg(&x[3 * ja + 0]), ya1 = __ldg(&x[3 * ja + 1]), ya2 = __ldg(&x[3 * ja + 2]);
    float xb0 = __ldg(&x[3 * ib + 0]), xb1 = __ldg(&x[3 * ib + 1]), xb2 = __ldg(&x[3 * ib + 2]);
    float yb0 = __ldg(&x[3 * jb + 0]), yb1 = __ldg(&x[3 * jb + 1]), yb2 = __ldg(&x[3 * jb + 2]);

    float da0 = xa0 - ya0, da1 = xa1 - ya1, da2 = xa2 - ya2;
    float db0 = xb0 - yb0, db1 = xb1 - yb1, db2 = xb2 - yb2;
    float nsq_a = da0 * da0 + da1 * da1 + da2 * da2;
    float nsq_b = db0 * db0 + db1 * db1 + db2 * db2;
    float dot_a = xa0 * ya0 + xa1 * ya1 + xa2 * ya2;
    float dot_b = xb0 * yb0 + xb1 * yb1 + xb2 * yb2;

    float na = log1pf(nsq_a);
    float nb = log1pf(nsq_b);
    float ta = copysignf(log1pf(fabsf(dot_a)), dot_a);
    float tb = copysignf(log1pf(fabsf(dot_b)), dot_b);

    // ---- fused layer1 + layer2 ----
    ull acc_a[H / 2], acc_b[H / 2];
    {
        const ull* b2p = (const ull*)sb2;
#pragma unroll
        for (int q = 0; q < H / 2; q++) { acc_a[q] = b2p[q]; acc_b[q] = b2p[q]; }
    }
#pragma unroll 2
    for (int j = 0; j < H; j++) {
        float4 c = sL1[j];
        float ha = fmaxf(fmaf(na, c.x, fmaf(ta, c.y, c.z)), 0.0f);
        float hb = fmaxf(fmaf(nb, c.x, fmaf(tb, c.y, c.z)), 0.0f);
        ull hap = pack2(ha, ha);
        ull hbp = pack2(hb, hb);
        const ulonglong2* row = (const ulonglong2*)(sW2 + j * H);
#pragma unroll
        for (int q = 0; q < H / 4; q++) {
            ulonglong2 w = row[q];                 // one load, two edges
            acc_a[2 * q + 0] = ffma2(hap, w.x, acc_a[2 * q + 0]);
            acc_a[2 * q + 1] = ffma2(hap, w.y, acc_a[2 * q + 1]);
            acc_b[2 * q + 0] = ffma2(hbp, w.x, acc_b[2 * q + 0]);
            acc_b[2 * q + 1] = ffma2(hbp, w.y, acc_b[2 * q + 1]);
        }
    }

    // ---- h2 = relu(acc), separate arrays (R8 exact) ----
    ull h2a[H / 2], h2b[H / 2];
#pragma unroll
    for (int q = 0; q < H / 2; q++) {
        float2 fa = unpack2(acc_a[q]);
        float2 fb = unpack2(acc_b[q]);
        h2a[q] = pack2(fmaxf(fa.x, 0.0f), fmaxf(fa.y, 0.0f));
        h2b[q] = pack2(fmaxf(fb.x, 0.0f), fmaxf(fb.y, 0.0f));
    }

    // ---- gate: wgt = sigmoid(h2 . W5 + b5) ----
    float wgt_a, wgt_b;
    {
        const ull* w5p = (const ull*)sW5;
        ull za0 = 0, za1 = 0, zb0 = 0, zb1 = 0;
#pragma unroll
        for (int q = 0; q < H / 2; q += 2) {
            za0 = ffma2(h2a[q], w5p[q], za0);
            za1 = ffma2(h2a[q + 1], w5p[q + 1], za1);
            zb0 = ffma2(h2b[q], w5p[q], zb0);
            zb1 = ffma2(h2b[q + 1], w5p[q + 1], zb1);
        }
        float2 fa = unpack2(fadd2(za0, za1));
        float2 fb = unpack2(fadd2(zb0, zb1));
        wgt_a = 1.0f / (1.0f + expf(-(fa.x + fa.y + sb5v)));
        wgt_b = 1.0f / (1.0f + expf(-(fb.x + fb.y + sb5v)));
    }

    // ---- m = h2 * wgt, write out ----
    {
        ull wpa = pack2(wgt_a, wgt_a);
        ull wpb = pack2(wgt_b, wgt_b);
        ulonglong2* moa = (ulonglong2*)(out_m + e0 * H);
        ulonglong2* mob = (ulonglong2*)(out_m + e1 * H);
#pragma unroll
        for (int q = 0; q < H / 4; q++) {
            ulonglong2 va, vb;
            va.x = fmul2(h2a[2 * q + 0], wpa);
            va.y = fmul2(h2a[2 * q + 1], wpa);
            vb.x = fmul2(h2b[2 * q + 0], wpb);
            vb.y = fmul2(h2b[2 * q + 1], wpb);
            moa[q] = va;
            mob[q] = vb;
        }
    }

    // ---- phi_x, k-outer vs transposed W3; rows shared by both edges ----
    float phix_a0 = 0.0f, phix_a1 = 0.0f, phix_b0 = 0.0f, phix_b1 = 0.0f;
#pragma unroll 2
    for (int k = 0; k < H; k++) {
        const ulonglong2* row = (const ulonglong2*)(sW3T + k * H);
        ull sa0 = 0, sa1 = 0, sb0 = 0, sb1 = 0;
#pragma unroll
        for (int q = 0; q < H / 4; q++) {
            ulonglong2 w = row[q];                 // one load, two edges
            sa0 = ffma2(h2a[2 * q + 0], w.x, sa0);
            sa1 = ffma2(h2a[2 * q + 1], w.y, sa1);
            sb0 = ffma2(h2b[2 * q + 0], w.x, sb0);
            sb1 = ffma2(h2b[2 * q + 1], w.y, sb1);
        }
        float2 fa = unpack2(fadd2(sa0, sa1));
        float2 fb = unpack2(fadd2(sb0, sb1));
        float a3a = fa.x + fa.y;
        float a3b = fb.x + fb.y;
        float b3k = sb3[k], w4k = sW4[k];
        float ua = fmaxf(fmaf(wgt_a, a3a, b3k), 0.0f);
        float ub = fmaxf(fmaf(wgt_b, a3b, b3k), 0.0f);
        if (k & 1) { phix_a1 = fmaf(ua, w4k, phix_a1); phix_b1 = fmaf(ub, w4k, phix_b1); }
        else       { phix_a0 = fmaf(ua, w4k, phix_a0); phix_b0 = fmaf(ub, w4k, phix_b0); }
    }
    float phix_a = phix_a0 + phix_a1;
    float phix_b = phix_b0 + phix_b1;

    // ---- scatter-mean: scalar reductions onto float4 cells ----
    float ua0 = fminf(fmaxf(da0 * phix_a, -100.0f), 100.0f);
    float ua1 = fminf(fmaxf(da1 * phix_a, -100.0f), 100.0f);
    float ua2 = fminf(fmaxf(da2 * phix_a, -100.0f), 100.0f);
    float ub0 = fminf(fmaxf(db0 * phix_b, -100.0f), 100.0f);
    float ub1 = fminf(fmaxf(db1 * phix_b, -100.0f), 100.0f);
    float ub2 = fminf(fmaxf(db2 * phix_b, -100.0f), 100.0f);
    float* ca = (float*)&g_sums4[ia];
    float* cb = (float*)&g_sums4[ib];
    atomicAdd(ca + 0, ua0);
    atomicAdd(ca + 1, ua1);
    atomicAdd(ca + 2, ua2);
    atomicAdd(ca + 3, 1.0f);
    atomicAdd(cb + 0, ub0);
    atomicAdd(cb + 1, ub1);
    atomicAdd(cb + 2, ub2);
    atomicAdd(cb + 3, 1.0f);
}

// ---------------------------------------------------------------------------
__global__ void node_kernel(const float* __restrict__ x, float* __restrict__ out_x) {
    int n = blockIdx.x * blockDim.x + threadIdx.x;
    if (n < NN) {
        float4 s = g_sums4[n];
        float inv = 1.0f / fmaxf(s.w, 1.0f);
        out_x[3 * n + 0] = x[3 * n + 0] + s.x * inv;
        out_x[3 * n + 1] = x[3 * n + 1] + s.y * inv;
        out_x[3 * n + 2] = x[3 * n + 2] + s.z * inv;
    }
}

// ---------------------------------------------------------------------------
extern "C" void kernel_launch(void* const* d_in, const int* in_sizes, int n_in,
                              void* d_out, int out_size) {
    const float* x   = (const float*)d_in[0];
    const int*   ei  = (const int*)d_in[1];     // int32 (jax default x64-disabled)
    const float* W1  = (const float*)d_in[2];
    const float* gma = (const float*)d_in[3];
    const float* bta = (const float*)d_in[4];
    const float* mea = (const float*)d_in[5];
    const float* var = (const float*)d_in[6];
    const float* W2  = (const float*)d_in[7];
    const float* b2  = (const float*)d_in[8];
    const float* W3  = (const float*)d_in[9];
    const float* b3  = (const float*)d_in[10];
    const float* W4  = (const float*)d_in[11];
    const float* W5  = (const float*)d_in[12];
    const float* b5  = (const float*)d_in[13];

    float* out_x = (float*)d_out;          // x_tilde: [NN, 3]
    float* out_m = out_x + (long)NN * 3;   // m: [NE, H]

    const int NBLK = NE / 512;             // 6250 blocks total (2 edges/thread)
    const int HALF = NBLK / 2;             // 3125 + 3125

    zero_kernel<<<(NN + 255) / 256, 256>>>();
    prep_kernel<<<1, 32>>>(W1, gma, bta, mea, var);
    // Split into two sequential launches: shifts ncu's -s 5 capture onto the
    // second edge launch (steady state) instead of node_kernel.
    edge_kernel<<<HALF, 256>>>(x, ei, W2, b2, W3, b3, W4, W5, b5, out_m, 0);
    edge_kernel<<<NBLK - HALF, 256>>>(x, ei, W2, b2, W3, b3, W4, W5, b5, out_m, HALF);
    node_kernel<<<(NN + 255) / 256, 256>>>(x, out_x);
}

// round 17
// speedup vs baseline: 1.6785x; 1.2515x over previous
#include <cuda_runtime.h>
#include <cstdint>

#define NN 100000
#define NE 3200000
#define H  32

typedef unsigned long long ull;

// ---- constant-bank weights (uniform-port LDCU, bypasses L1TEX) ----
__constant__ float4 cL1[H];            // (A,B,C,0): h1 = relu(A*n + B*t + C)
__constant__ float  cW2[H * H];        // row-major [j][k]
__constant__ float  cW3T[H * H];       // transposed [k][j]
__constant__ float  cb2[H], cb3[H], cW4[H], cW5[H];
__constant__ float  cb5;

// ---- __device__ staging (prep output -> memcpy into constant) ----
__device__ float4 g_L1q[H];
__device__ float  g_W3T[H * H];
__device__ __align__(16) float4 g_sums4[NN];   // xyz = sums, w = count

// ---- packed f32x2 helpers (ptxas will not auto-fuse these) ----
__device__ __forceinline__ ull ffma2(ull a, ull b, ull c) {
    ull d;
    asm("fma.rn.f32x2 %0, %1, %2, %3;" : "=l"(d) : "l"(a), "l"(b), "l"(c));
    return d;
}
__device__ __forceinline__ ull fmul2(ull a, ull b) {
    ull d;
    asm("mul.rn.f32x2 %0, %1, %2;" : "=l"(d) : "l"(a), "l"(b));
    return d;
}
__device__ __forceinline__ ull fadd2(ull a, ull b) {
    ull d;
    asm("add.rn.f32x2 %0, %1, %2;" : "=l"(d) : "l"(a), "l"(b));
    return d;
}
__device__ __forceinline__ ull pack2(float lo, float hi) {
    ull r;
    asm("mov.b64 %0, {%1, %2};" : "=l"(r) : "f"(lo), "f"(hi));
    return r;
}
__device__ __forceinline__ float2 unpack2(ull v) {
    float2 f;
    asm("mov.b64 {%0, %1}, %2;" : "=f"(f.x), "=f"(f.y) : "l"(v));
    return f;
}

// ---------------------------------------------------------------------------
// BN fold + W3 transpose into staging globals (copied to __constant__ after).
__global__ void prep_kernel(const float* __restrict__ W1,
                            const float* __restrict__ gamma,
                            const float* __restrict__ beta,
                            const float* __restrict__ mean,
                            const float* __restrict__ var,
                            const float* __restrict__ W3) {
    int t = threadIdx.x;                          // 1024 threads
    if (t < H) {
        float s = gamma[t] * rsqrtf(var[t] + 1e-5f);
        g_L1q[t] = make_float4(W1[t] * s, W1[H + t] * s, beta[t] - mean[t] * s, 0.0f);
    }
    if (t < H * H) {
        int k = t >> 5, j = t & 31;
        g_W3T[t] = W3[j * H + k];
    }
}

__global__ void zero_kernel() {
    int i = blockIdx.x * blockDim.x + threadIdx.x;
    if (i < NN) g_sums4[i] = make_float4(0.0f, 0.0f, 0.0f, 0.0f);
}

// ---------------------------------------------------------------------------
// TWO edges per thread. All weight reads hit the constant bank (immediate
// offsets after full unroll -> uniform LDCU, off the L1TEX critical path).
// No shared memory, no __syncthreads.
__global__ void __launch_bounds__(256, 2) edge_kernel(
    const float* __restrict__ x,
    const int* __restrict__ ei,
    float* __restrict__ out_m, int blk0)
{
    int tid = threadIdx.x;
    long e0 = ((long)(blockIdx.x + blk0) * 256 + tid) * 2;
    long e1 = e0 + 1;

    int2 di = *(const int2*)(ei + e0);
    int2 sj = *(const int2*)(ei + (long)NE + e0);
    int ia = di.x, ib = di.y, ja = sj.x, jb = sj.y;
    if ((unsigned)ia >= NN || (unsigned)ib >= NN ||
        (unsigned)ja >= NN || (unsigned)jb >= NN) return;

    float xa0 = __ldg(&x[3 * ia + 0]), xa1 = __ldg(&x[3 * ia + 1]), xa2 = __ldg(&x[3 * ia + 2]);
    float ya0 = __ldg(&x[3 * ja + 0]), ya1 = __ldg(&x[3 * ja + 1]), ya2 = __ldg(&x[3 * ja + 2]);
    float xb0 = __ldg(&x[3 * ib + 0]), xb1 = __ldg(&x[3 * ib + 1]), xb2 = __ldg(&x[3 * ib + 2]);
    float yb0 = __ldg(&x[3 * jb + 0]), yb1 = __ldg(&x[3 * jb + 1]), yb2 = __ldg(&x[3 * jb + 2]);

    float da0 = xa0 - ya0, da1 = xa1 - ya1, da2 = xa2 - ya2;
    float db0 = xb0 - yb0, db1 = xb1 - yb1, db2 = xb2 - yb2;
    float nsq_a = da0 * da0 + da1 * da1 + da2 * da2;
    float nsq_b = db0 * db0 + db1 * db1 + db2 * db2;
    float dot_a = xa0 * ya0 + xa1 * ya1 + xa2 * ya2;
    float dot_b = xb0 * yb0 + xb1 * yb1 + xb2 * yb2;

    float na = log1pf(nsq_a);
    float nb = log1pf(nsq_b);
    float ta = copysignf(log1pf(fabsf(dot_a)), dot_a);
    float tb = copysignf(log1pf(fabsf(dot_b)), dot_b);

    // ---- fused layer1 + layer2: acc = b2 + sum_j relu(l1_j) * W2[j,:] ----
    ull acc_a[H / 2], acc_b[H / 2];
    {
        const ull* b2p = (const ull*)cb2;
#pragma unroll
        for (int q = 0; q < H / 2; q++) { acc_a[q] = b2p[q]; acc_b[q] = b2p[q]; }
    }
#pragma unroll
    for (int j = 0; j < H; j++) {
        float4 c = cL1[j];
        float ha = fmaxf(fmaf(na, c.x, fmaf(ta, c.y, c.z)), 0.0f);
        float hb = fmaxf(fmaf(nb, c.x, fmaf(tb, c.y, c.z)), 0.0f);
        ull hap = pack2(ha, ha);
        ull hbp = pack2(hb, hb);
        const ulonglong2* row = (const ulonglong2*)(cW2 + j * H);
#pragma unroll
        for (int q = 0; q < H / 4; q++) {
            ulonglong2 w = row[q];                 // constant bank, imm offset
            acc_a[2 * q + 0] = ffma2(hap, w.x, acc_a[2 * q + 0]);
            acc_a[2 * q + 1] = ffma2(hap, w.y, acc_a[2 * q + 1]);
            acc_b[2 * q + 0] = ffma2(hbp, w.x, acc_b[2 * q + 0]);
            acc_b[2 * q + 1] = ffma2(hbp, w.y, acc_b[2 * q + 1]);
        }
    }

    // ---- h2 = relu(acc) ----
    ull h2a[H / 2], h2b[H / 2];
#pragma unroll
    for (int q = 0; q < H / 2; q++) {
        float2 fa = unpack2(acc_a[q]);
        float2 fb = unpack2(acc_b[q]);
        h2a[q] = pack2(fmaxf(fa.x, 0.0f), fmaxf(fa.y, 0.0f));
        h2b[q] = pack2(fmaxf(fb.x, 0.0f), fmaxf(fb.y, 0.0f));
    }

    // ---- gate: wgt = sigmoid(h2 . W5 + b5) ----
    float wgt_a, wgt_b;
    {
        const ull* w5p = (const ull*)cW5;
        ull za0 = 0, za1 = 0, zb0 = 0, zb1 = 0;
#pragma unroll
        for (int q = 0; q < H / 2; q += 2) {
            za0 = ffma2(h2a[q], w5p[q], za0);
            za1 = ffma2(h2a[q + 1], w5p[q + 1], za1);
            zb0 = ffma2(h2b[q], w5p[q], zb0);
            zb1 = ffma2(h2b[q + 1], w5p[q + 1], zb1);
        }
        float2 fa = unpack2(fadd2(za0, za1));
        float2 fb = unpack2(fadd2(zb0, zb1));
        wgt_a = 1.0f / (1.0f + expf(-(fa.x + fa.y + cb5)));
        wgt_b = 1.0f / (1.0f + expf(-(fb.x + fb.y + cb5)));
    }

    // ---- m = h2 * wgt, write out ----
    {
        ull wpa = pack2(wgt_a, wgt_a);
        ull wpb = pack2(wgt_b, wgt_b);
        ulonglong2* moa = (ulonglong2*)(out_m + e0 * H);
        ulonglong2* mob = (ulonglong2*)(out_m + e1 * H);
#pragma unroll
        for (int q = 0; q < H / 4; q++) {
            ulonglong2 va, vb;
            va.x = fmul2(h2a[2 * q + 0], wpa);
            va.y = fmul2(h2a[2 * q + 1], wpa);
            vb.x = fmul2(h2b[2 * q + 0], wpb);
            vb.y = fmul2(h2b[2 * q + 1], wpb);
            moa[q] = va;
            mob[q] = vb;
        }
    }

    // ---- phi_x, k-outer vs transposed W3 (constant bank) ----
    float phix_a0 = 0.0f, phix_a1 = 0.0f, phix_b0 = 0.0f, phix_b1 = 0.0f;
#pragma unroll
    for (int k = 0; k < H; k++) {
        const ulonglong2* row = (const ulonglong2*)(cW3T + k * H);
        ull sa0 = 0, sa1 = 0, sb0 = 0, sb1 = 0;
#pragma unroll
        for (int q = 0; q < H / 4; q++) {
            ulonglong2 w = row[q];                 // constant bank, imm offset
            sa0 = ffma2(h2a[2 * q + 0], w.x, sa0);
            sa1 = ffma2(h2a[2 * q + 1], w.y, sa1);
            sb0 = ffma2(h2b[2 * q + 0], w.x, sb0);
            sb1 = ffma2(h2b[2 * q + 1], w.y, sb1);
        }
        float2 fa = unpack2(fadd2(sa0, sa1));
        float2 fb = unpack2(fadd2(sb0, sb1));
        float a3a = fa.x + fa.y;
        float a3b = fb.x + fb.y;
        float b3k = cb3[k], w4k = cW4[k];
        float ua = fmaxf(fmaf(wgt_a, a3a, b3k), 0.0f);
        float ub = fmaxf(fmaf(wgt_b, a3b, b3k), 0.0f);
        if (k & 1) { phix_a1 = fmaf(ua, w4k, phix_a1); phix_b1 = fmaf(ub, w4k, phix_b1); }
        else       { phix_a0 = fmaf(ua, w4k, phix_a0); phix_b0 = fmaf(ub, w4k, phix_b0); }
    }
    float phix_a = phix_a0 + phix_a1;
    float phix_b = phix_b0 + phix_b1;

    // ---- scatter-mean: scalar reductions onto float4 cells ----
    float ua0 = fminf(fmaxf(da0 * phix_a, -100.0f), 100.0f);
    float ua1 = fminf(fmaxf(da1 * phix_a, -100.0f), 100.0f);
    float ua2 = fminf(fmaxf(da2 * phix_a, -100.0f), 100.0f);
    float ub0 = fminf(fmaxf(db0 * phix_b, -100.0f), 100.0f);
    float ub1 = fminf(fmaxf(db1 * phix_b, -100.0f), 100.0f);
    float ub2 = fminf(fmaxf(db2 * phix_b, -100.0f), 100.0f);
    float* ca = (float*)&g_sums4[ia];
    float* cb = (float*)&g_sums4[ib];
    atomicAdd(ca + 0, ua0);
    atomicAdd(ca + 1, ua1);
    atomicAdd(ca + 2, ua2);
    atomicAdd(ca + 3, 1.0f);
    atomicAdd(cb + 0, ub0);
    atomicAdd(cb + 1, ub1);
    atomicAdd(cb + 2, ub2);
    atomicAdd(cb + 3, 1.0f);
}

// ---------------------------------------------------------------------------
__global__ void node_kernel(const float* __restrict__ x, float* __restrict__ out_x) {
    int n = blockIdx.x * blockDim.x + threadIdx.x;
    if (n < NN) {
        float4 s = g_sums4[n];
        float inv = 1.0f / fmaxf(s.w, 1.0f);
        out_x[3 * n + 0] = x[3 * n + 0] + s.x * inv;
        out_x[3 * n + 1] = x[3 * n + 1] + s.y * inv;
        out_x[3 * n + 2] = x[3 * n + 2] + s.z * inv;
    }
}

// ---------------------------------------------------------------------------
extern "C" void kernel_launch(void* const* d_in, const int* in_sizes, int n_in,
                              void* d_out, int out_size) {
    const float* x   = (const float*)d_in[0];
    const int*   ei  = (const int*)d_in[1];     // int32 (jax default x64-disabled)
    const float* W1  = (const float*)d_in[2];
    const float* gma = (const float*)d_in[3];
    const float* bta = (const float*)d_in[4];
    const float* mea = (const float*)d_in[5];
    const float* var = (const float*)d_in[6];
    const float* W2  = (const float*)d_in[7];
    const float* b2  = (const float*)d_in[8];
    const float* W3  = (const float*)d_in[9];
    const float* b3  = (const float*)d_in[10];
    const float* W4  = (const float*)d_in[11];
    const float* W5  = (const float*)d_in[12];
    const float* b5  = (const float*)d_in[13];

    float* out_x = (float*)d_out;          // x_tilde: [NN, 3]
    float* out_m = out_x + (long)NN * 3;   // m: [NE, H]

    const int NBLK = NE / 512;             // 2 edges/thread
    const int HALF = NBLK / 2;

    zero_kernel<<<(NN + 255) / 256, 256>>>();
    prep_kernel<<<1, 1024>>>(W1, gma, bta, mea, var, W3);

    // Stage constants (all D2D async memcpys — graph-capturable, no allocs).
    void* pL1 = nullptr; void* pW3T = nullptr;
    cudaGetSymbolAddress(&pL1, g_L1q);
    cudaGetSymbolAddress(&pW3T, g_W3T);
    cudaMemcpyToSymbolAsync(cL1, pL1, H * sizeof(float4), 0, cudaMemcpyDeviceToDevice, 0);
    cudaMemcpyToSymbolAsync(cW3T, pW3T, H * H * sizeof(float), 0, cudaMemcpyDeviceToDevice, 0);
    cudaMemcpyToSymbolAsync(cW2, W2, H * H * sizeof(float), 0, cudaMemcpyDeviceToDevice, 0);
    cudaMemcpyToSymbolAsync(cb2, b2, H * sizeof(float), 0, cudaMemcpyDeviceToDevice, 0);
    cudaMemcpyToSymbolAsync(cb3, b3, H * sizeof(float), 0, cudaMemcpyDeviceToDevice, 0);
    cudaMemcpyToSymbolAsync(cW4, W4, H * sizeof(float), 0, cudaMemcpyDeviceToDevice, 0);
    cudaMemcpyToSymbolAsync(cW5, W5, H * sizeof(float), 0, cudaMemcpyDeviceToDevice, 0);
    cudaMemcpyToSymbolAsync(cb5, b5, sizeof(float), 0, cudaMemcpyDeviceToDevice, 0);

    // Split edge grid: keeps 5 kernel launches/call so ncu -s 5 -c 1 lands on
    // the steady-state second edge launch.
    edge_kernel<<<HALF, 256>>>(x, ei, out_m, 0);
    edge_kernel<<<NBLK - HALF, 256>>>(x, ei, out_m, HALF);
    node_kernel<<<(NN + 255) / 256, 256>>>(x, out_x);
}